// round 14
// baseline (speedup 1.0000x reference)
#include <cuda_runtime.h>
#include <cuda_fp16.h>
#include <math.h>
#include <stdint.h>

// ---------------------------------------------------------------------------
// Problem constants
// ---------------------------------------------------------------------------
namespace {
constexpr int BATCH = 128;
constexpr int LC    = 64;
constexpr int LQ    = 448;
constexpr int DIM   = 768;
constexpr int SEQ   = 512;
constexpr int C4    = 3072;
constexpr int SEi   = DIM * LC;

constexpr long long SZ_C1 = (long long)BATCH * LC;
constexpr long long SZ_Q2 = (long long)BATCH * LQ;
constexpr long long SZ_BD = (long long)BATCH * LC * DIM;
constexpr long long SZ_S  = (long long)BATCH * LC * LQ;
constexpr long long SZ_Y  = (long long)BATCH * LC * C4;
constexpr long long SZ_E  = SZ_BD;
constexpr long long SZ_Q  = (long long)BATCH * LQ * DIM;
constexpr long long SE    = (long long)DIM * LC;

constexpr long long OFF_C1  = 0;
constexpr long long OFF_Q2  = OFF_C1 + SZ_C1;
constexpr long long OFF_CW3 = OFF_Q2 + SZ_Q2;
constexpr long long OFF_S   = OFF_CW3 + SZ_BD;   // S fp16
constexpr long long OFF_S1  = OFF_S  + SZ_S;     // S1 fp16
constexpr long long OFF_S2  = OFF_S1 + SZ_S;     // S2 fp16
constexpr long long OFF_A   = OFF_S2 + SZ_S;
constexpr long long OFF_T   = OFF_A  + SZ_BD;
constexpr long long OFF_BT  = OFF_T  + (long long)BATCH * LC * LC;
constexpr long long OFF_Y   = OFF_BT + SZ_BD;
constexpr long long OFF_E0  = OFF_Y  + SZ_Y;
constexpr long long OFF_PE   = OFF_E0 + 8 * SZ_E;
constexpr long long OFF_PS   = OFF_PE + (long long)DIM * LC;
constexpr long long OFF_ACT  = OFF_PS + 2048;
constexpr long long OFF_WB   = OFF_ACT + 2 * SZ_BD;
constexpr long long WB_FLOATS = ((long long)DIM * C4 + 7LL * DIM * DIM) / 2 + 64;
constexpr long long OFF_QS   = OFF_WB + WB_FLOATS;
constexpr long long OFF_QT   = OFF_QS + SZ_Q;
constexpr long long POOL_SZ  = OFF_QT + SZ_Q;

constexpr int NCHUNK = DIM / 64;   // 12 partial chunks (q2 / c1)
} // namespace

__device__ float g_pool[POOL_SZ];

// ---------------------------------------------------------------------------
// Family-portable tensor-core primitives
// ---------------------------------------------------------------------------
__device__ __forceinline__ uint32_t smem_u32(const void* p) {
    uint32_t a;
    asm("{ .reg .u64 t; cvta.to.shared.u64 t, %1; cvt.u32.u64 %0, t; }" : "=r"(a) : "l"(p));
    return a;
}
#define SW128(o) ((o) ^ (((o) >> 3) & 0x70))

__device__ __forceinline__ void cpa16(uint32_t dst, const void* src) {
    asm volatile("cp.async.cg.shared.global [%0], [%1], 16;" :: "r"(dst), "l"(src) : "memory");
}
__device__ __forceinline__ void cp_commit() {
    asm volatile("cp.async.commit_group;" ::: "memory");
}
__device__ __forceinline__ void cp_wait1() {
    asm volatile("cp.async.wait_group 1;" ::: "memory");
}
__device__ __forceinline__ void cp_wait0() {
    asm volatile("cp.async.wait_group 0;" ::: "memory");
}
__device__ __forceinline__ void ldsm4(uint32_t* r, uint32_t a) {
    asm volatile("ldmatrix.sync.aligned.m8n8.x4.shared.b16 {%0,%1,%2,%3}, [%4];"
        : "=r"(r[0]), "=r"(r[1]), "=r"(r[2]), "=r"(r[3]) : "r"(a));
}
__device__ __forceinline__ void mma_f16(float* d, const uint32_t* a, uint32_t b0, uint32_t b1) {
    asm volatile("mma.sync.aligned.m16n8k16.row.col.f32.f16.f16.f32 "
        "{%0,%1,%2,%3}, {%4,%5,%6,%7}, {%8,%9}, {%0,%1,%2,%3};"
        : "+f"(d[0]), "+f"(d[1]), "+f"(d[2]), "+f"(d[3])
        : "r"(a[0]), "r"(a[1]), "r"(a[2]), "r"(a[3]), "r"(b0), "r"(b1));
}

// ---------------------------------------------------------------------------
// mgemm: batch-shared-B tensor GEMM (fp16 in, fp32 accum), 2 CTA/SM
// ---------------------------------------------------------------------------
namespace {
constexpr int MT_TILE = 16384;
constexpr int MT_SMEM = 3 * 2 * MT_TILE + 1024;
constexpr int PG_TILE = 8192;
constexpr int PG_SMEM = 2 * 2 * PG_TILE + 1024;
constexpr int RZ_SMEM = 3 * 64 * 128 * 4 + 16;
constexpr int SB_SMEM = (64 * 449 + 64 * 3 + 448 + 16) * 4;   // ~118 KB
}

template<int OMODE>
__global__ void __launch_bounds__(256, 2) mgemm_k(
    const __half* __restrict__ Af,
    const __half* __restrict__ Bf,
    float* __restrict__ O, __half* __restrict__ Oh, long long sO, int ldo,
    const float* __restrict__ bias,
    const float* __restrict__ R, long long sR,
    const float* __restrict__ plane,
    float* __restrict__ psum,
    int K, int relu)
{
    extern __shared__ char dsm[];
    const uint32_t tb = (smem_u32(dsm) + 1023u) & ~1023u;

    const int tid = threadIdx.x, lane = tid & 31, wid = tid >> 5;
    const int n0 = blockIdx.x * 128;
    const int rbase = blockIdx.y * 128;
    const int wm = wid & 1, wn = wid >> 1;

    float acc[4][4][4];
#pragma unroll
    for (int a = 0; a < 4; a++)
#pragma unroll
        for (int b = 0; b < 4; b++)
#pragma unroll
            for (int c = 0; c < 4; c++) acc[a][b][c] = 0.f;

    const int nch = K / 64;

    auto copy_chunk = [&](int ci, int s) {
        const int k0 = ci * 64;
        const uint32_t tA = tb + (s * 2 + 0) * MT_TILE;
        const uint32_t tB = tb + (s * 2 + 1) * MT_TILE;
#pragma unroll
        for (int it = 0; it < 4; it++) {
            int idx = tid + it * 256;
            int r = idx >> 3, c = idx & 7;
            uint32_t doff = SW128((uint32_t)(r * 128 + c * 16));
            cpa16(tA + doff, Af + (long long)(rbase + r) * K + k0 + c * 8);
            cpa16(tB + doff, Bf + (long long)(n0 + r) * K + k0 + c * 8);
        }
    };

    copy_chunk(0, 0); cp_commit();
    copy_chunk(1, 1); cp_commit();

    const int rl = lane & 15, chalf = lane >> 4;

    for (int i = 0; i < nch; i++) {
        if (i + 1 < nch) cp_wait1(); else cp_wait0();
        __syncthreads();
        if (i + 2 < nch) { copy_chunk(i + 2, (i + 2) % 3); cp_commit(); }

        const int s = i % 3;
        const uint32_t tA = tb + (s * 2 + 0) * MT_TILE;
        const uint32_t tB = tb + (s * 2 + 1) * MT_TILE;

#pragma unroll
        for (int ks = 0; ks < 4; ks++) {
            const uint32_t coff = (uint32_t)((ks * 2 + chalf) * 16);
            uint32_t af[4][4], bf[2][4];
#pragma unroll
            for (int mt = 0; mt < 4; mt++) {
                uint32_t off = SW128((uint32_t)((wm * 64 + mt * 16 + rl) * 128) + coff);
                ldsm4(af[mt], tA + off);
            }
#pragma unroll
            for (int np = 0; np < 2; np++) {
                uint32_t off = SW128((uint32_t)((wn * 32 + np * 16 + rl) * 128) + coff);
                ldsm4(bf[np], tB + off);
            }
#pragma unroll
            for (int mt = 0; mt < 4; mt++)
#pragma unroll
                for (int np = 0; np < 2; np++)
#pragma unroll
                    for (int j = 0; j < 2; j++)
                        mma_f16(acc[mt][np * 2 + j], af[mt], bf[np][j], bf[np][j + 2]);
        }
    }

    const int b0 = blockIdx.y * 2;
    float ls = 0.f, ls2 = 0.f;
#pragma unroll
    for (int mt = 0; mt < 4; mt++) {
        int row0 = wm * 64 + mt * 16 + (lane >> 2);
#pragma unroll
        for (int half = 0; half < 2; half++) {
            int row = row0 + half * 8;
            int bi = b0 + (row >> 6), l = row & 63;
            float* Ob = O ? O + (long long)bi * sO : nullptr;
            __half* Ohb = Oh ? Oh + (long long)bi * sO : nullptr;
            const float* Rb = R ? R + (long long)bi * sR : nullptr;
#pragma unroll
            for (int nn = 0; nn < 4; nn++) {
                int n = n0 + wn * 32 + nn * 8 + (lane & 3) * 2;
#pragma unroll
                for (int e = 0; e < 2; e++) {
                    float v = acc[mt][nn][half * 2 + e];
                    int nc = n + e;
                    if (bias) v += bias[nc];
                    if (relu) v = fmaxf(v, 0.f);
                    long long o = (OMODE == 1) ? ((long long)nc * 64 + l)
                                               : ((long long)l * ldo + nc);
                    if (Rb)    v += Rb[o];
                    if (plane) v += plane[o];
                    if (Ohb) Ohb[o] = __float2half(v);
                    else     Ob[o]  = v;
                    if (psum) { ls += v; ls2 += v * v; }
                }
            }
        }
    }

    if (psum) {
#pragma unroll
        for (int o = 16; o > 0; o >>= 1) {
            ls  += __shfl_down_sync(0xffffffffu, ls, o);
            ls2 += __shfl_down_sync(0xffffffffu, ls2, o);
        }
        __shared__ float wsum[8], wsum2[8];
        if (lane == 0) { wsum[wid] = ls; wsum2[wid] = ls2; }
        __syncthreads();
        if (tid < 2) {
            float a  = wsum[tid]  + wsum[tid + 2]  + wsum[tid + 4]  + wsum[tid + 6];
            float a2 = wsum2[tid] + wsum2[tid + 2] + wsum2[tid + 4] + wsum2[tid + 6];
            long long o = ((long long)(b0 + tid) * gridDim.x + blockIdx.x) * 2;
            psum[o] = a; psum[o + 1] = a2;
        }
    }
}

// ---------------------------------------------------------------------------
// pgemm: per-batch GEMM, fp16 in, fp32 accum. Optional fp16 out.
// ---------------------------------------------------------------------------
__global__ void __launch_bounds__(256) pgemm_k(
    const __half* __restrict__ Af, long long sA, int lda,
    const __half* __restrict__ Bf, long long sB, int ldb,
    float* __restrict__ O, __half* __restrict__ Oh, long long sO, int ldo,
    const float* __restrict__ bM, long long sbM,
    const float* __restrict__ bN, long long sbN,
    float alpha, int K)
{
    extern __shared__ char dsm[];
    const uint32_t tb = (smem_u32(dsm) + 1023u) & ~1023u;

    const int tid = threadIdx.x, lane = tid & 31, wid = tid >> 5;
    const int n0 = blockIdx.x * 64;
    const int b  = blockIdx.y;
    const int wm = wid >> 1, wn = wid & 1;

    const __half* Afb = Af + (long long)b * sA;
    const __half* Bfb = Bf + (long long)b * sB + (long long)n0 * ldb;

    float acc[4][4];
#pragma unroll
    for (int a = 0; a < 4; a++)
#pragma unroll
        for (int c = 0; c < 4; c++) acc[a][c] = 0.f;

    const int nch = K / 64;

    auto copy_chunk = [&](int ci, int s) {
        const int k0 = ci * 64;
        const uint32_t tA = tb + (s * 2 + 0) * PG_TILE;
        const uint32_t tB = tb + (s * 2 + 1) * PG_TILE;
#pragma unroll
        for (int it = 0; it < 2; it++) {
            int idx = tid + it * 256;
            int r = idx >> 3, c = idx & 7;
            uint32_t doff = SW128((uint32_t)(r * 128 + c * 16));
            cpa16(tA + doff, Afb + (long long)r * lda + k0 + c * 8);
            cpa16(tB + doff, Bfb + (long long)r * ldb + k0 + c * 8);
        }
    };

    copy_chunk(0, 0); cp_commit();

    const int rl = lane & 15, chalf = lane >> 4;

    for (int i = 0; i < nch; i++) {
        cp_wait0();
        __syncthreads();
        if (i + 1 < nch) { copy_chunk(i + 1, (i + 1) & 1); cp_commit(); }

        const int s = i & 1;
        const uint32_t tA = tb + (s * 2 + 0) * PG_TILE;
        const uint32_t tB = tb + (s * 2 + 1) * PG_TILE;

#pragma unroll
        for (int ks = 0; ks < 4; ks++) {
            const uint32_t coff = (uint32_t)((ks * 2 + chalf) * 16);
            uint32_t af[4], bf[2][4];
            {
                uint32_t off = SW128((uint32_t)((wm * 16 + rl) * 128) + coff);
                ldsm4(af, tA + off);
            }
#pragma unroll
            for (int np = 0; np < 2; np++) {
                uint32_t off = SW128((uint32_t)((wn * 32 + np * 16 + rl) * 128) + coff);
                ldsm4(bf[np], tB + off);
            }
#pragma unroll
            for (int np = 0; np < 2; np++)
#pragma unroll
                for (int j = 0; j < 2; j++)
                    mma_f16(acc[np * 2 + j], af, bf[np][j], bf[np][j + 2]);
        }
    }

    float* Ob = O ? O + (long long)b * sO : nullptr;
    __half* Ohb = Oh ? Oh + (long long)b * sO : nullptr;
    const float* bMp = bM ? bM + (long long)b * sbM : nullptr;
    const float* bNp = bN ? bN + (long long)b * sbN : nullptr;
#pragma unroll
    for (int half = 0; half < 2; half++) {
        int row = wm * 16 + (lane >> 2) + half * 8;
#pragma unroll
        for (int nn = 0; nn < 4; nn++) {
            int n = n0 + wn * 32 + nn * 8 + (lane & 3) * 2;
#pragma unroll
            for (int e = 0; e < 2; e++) {
                float v = acc[nn][half * 2 + e] * alpha;
                int nc = n + e;
                if (bMp) v += bMp[row];
                if (bNp) v += bNp[nc];
                long long o = (long long)row * ldo + nc;
                if (Ohb) Ohb[o] = __float2half(v);
                else     Ob[o]  = v;
            }
        }
    }
}

// ---------------------------------------------------------------------------
// pgemm_sm: per-batch 64x64 GEMM + fused row softmax -> fp16 attn
// ---------------------------------------------------------------------------
__global__ void __launch_bounds__(256) pgemm_sm_k(
    const __half* __restrict__ Af, long long sA, int lda,
    const __half* __restrict__ Bf, long long sB, int ldb,
    __half* __restrict__ Oh, long long sO,
    float alpha, int K)
{
    extern __shared__ char dsm[];
    const uint32_t tb = (smem_u32(dsm) + 1023u) & ~1023u;
    __shared__ float ss[64][65];
    __shared__ float rinv[64];

    const int tid = threadIdx.x, lane = tid & 31, wid = tid >> 5;
    const int b  = blockIdx.y;
    const int wm = wid >> 1, wn = wid & 1;

    const __half* Afb = Af + (long long)b * sA;
    const __half* Bfb = Bf + (long long)b * sB;

    float acc[4][4];
#pragma unroll
    for (int a = 0; a < 4; a++)
#pragma unroll
        for (int c = 0; c < 4; c++) acc[a][c] = 0.f;

    const int nch = K / 64;

    auto copy_chunk = [&](int ci, int s) {
        const int k0 = ci * 64;
        const uint32_t tA = tb + (s * 2 + 0) * PG_TILE;
        const uint32_t tB = tb + (s * 2 + 1) * PG_TILE;
#pragma unroll
        for (int it = 0; it < 2; it++) {
            int idx = tid + it * 256;
            int r = idx >> 3, c = idx & 7;
            uint32_t doff = SW128((uint32_t)(r * 128 + c * 16));
            cpa16(tA + doff, Afb + (long long)r * lda + k0 + c * 8);
            cpa16(tB + doff, Bfb + (long long)r * ldb + k0 + c * 8);
        }
    };

    copy_chunk(0, 0); cp_commit();

    const int rl = lane & 15, chalf = lane >> 4;

    for (int i = 0; i < nch; i++) {
        cp_wait0();
        __syncthreads();
        if (i + 1 < nch) { copy_chunk(i + 1, (i + 1) & 1); cp_commit(); }

        const int s = i & 1;
        const uint32_t tA = tb + (s * 2 + 0) * PG_TILE;
        const uint32_t tB = tb + (s * 2 + 1) * PG_TILE;

#pragma unroll
        for (int ks = 0; ks < 4; ks++) {
            const uint32_t coff = (uint32_t)((ks * 2 + chalf) * 16);
            uint32_t af[4], bf[2][4];
            {
                uint32_t off = SW128((uint32_t)((wm * 16 + rl) * 128) + coff);
                ldsm4(af, tA + off);
            }
#pragma unroll
            for (int np = 0; np < 2; np++) {
                uint32_t off = SW128((uint32_t)((wn * 32 + np * 16 + rl) * 128) + coff);
                ldsm4(bf[np], tB + off);
            }
#pragma unroll
            for (int np = 0; np < 2; np++)
#pragma unroll
                for (int j = 0; j < 2; j++)
                    mma_f16(acc[np * 2 + j], af, bf[np][j], bf[np][j + 2]);
        }
    }

#pragma unroll
    for (int half = 0; half < 2; half++) {
        int row = wm * 16 + (lane >> 2) + half * 8;
#pragma unroll
        for (int nn = 0; nn < 4; nn++) {
            int n = wn * 32 + nn * 8 + (lane & 3) * 2;
#pragma unroll
            for (int e = 0; e < 2; e++)
                ss[row][n + e] = acc[nn][half * 2 + e] * alpha;
        }
    }
    __syncthreads();

    if (tid < 64) {
        float m = -1e30f;
#pragma unroll 8
        for (int c = 0; c < 64; c++) m = fmaxf(m, ss[tid][c]);
        float s = 0.f;
#pragma unroll 8
        for (int c = 0; c < 64; c++) { float e = expf(ss[tid][c] - m); ss[tid][c] = e; s += e; }
        rinv[tid] = 1.f / s;
    }
    __syncthreads();

    __half* Ohb = Oh + (long long)b * sO;
#pragma unroll
    for (int it = 0; it < 16; it++) {
        int idx = tid + it * 256;
        int r = idx >> 6, c = idx & 63;
        Ohb[idx] = __float2half(ss[r][c] * rinv[r]);
    }
}

// ---------------------------------------------------------------------------
// LN apply kernels (stats finalized inline from mgemm psum partials)
// ---------------------------------------------------------------------------
__device__ __forceinline__ void ln_stats_from_psum(const float* ps, int b,
                                                   float& mu, float& rs)
{
    __shared__ float smu, srs;
    if (threadIdx.x == 0) {
        float s = 0.f, s2 = 0.f;
#pragma unroll
        for (int i = 0; i < 6; i++) {
            s  += ps[((long long)b * 6 + i) * 2];
            s2 += ps[((long long)b * 6 + i) * 2 + 1];
        }
        float m = s / (float)SEi;
        smu = m;
        srs = rsqrtf(s2 / (float)SEi - m * m + 1e-5f);
    }
    __syncthreads();
    mu = smu; rs = srs;
}

__global__ void ln_conv_t_k(const float* __restrict__ in, const float* __restrict__ ps,
                            const float* __restrict__ lw,
                            const float* __restrict__ lb, const float* __restrict__ cw,
                            const float* __restrict__ cb,
                            __half* __restrict__ out)
{
    __shared__ float sm[32][65];
    int b = blockIdx.x, d0 = blockIdx.y * 32;
    float mu, rs;
    ln_stats_from_psum(ps, b, mu, rs);
    const float* ib = in + (long long)b * (DIM * LC);
#pragma unroll
    for (int it = 0; it < 8; it++) {
        int idx = threadIdx.x + it * 256;
        int dd = idx >> 6, l = idx & 63;
        int d = d0 + dd;
        const float* rowp = ib + (long long)d * 64;
        int wb = d * 64;
        float a = cb[d];
#pragma unroll
        for (int t = 0; t < 3; t++) {
            int l2 = l + t - 1;
            if (l2 < 0 || l2 >= 64) continue;
            float v = (rowp[l2] - mu) * rs * lw[wb + l2] + lb[wb + l2];
            a = fmaf(v, cw[d * 3 + t], a);
        }
        sm[dd][l] = a;
    }
    __syncthreads();
    __half* ob = out + (long long)b * 64 * 768;
#pragma unroll
    for (int it = 0; it < 8; it++) {
        int idx = threadIdx.x + it * 256;
        int l = idx >> 5, dd = idx & 31;
        ob[(long long)l * 768 + d0 + dd] = __float2half(sm[dd][l]);
    }
}

__global__ void ln_apply_t_k(const float* __restrict__ in, const float* __restrict__ ps,
                             const float* __restrict__ lw,
                             const float* __restrict__ lb,
                             __half* __restrict__ out)
{
    __shared__ float sm[32][65];
    int b = blockIdx.x, d0 = blockIdx.y * 32;
    float mu, rs;
    ln_stats_from_psum(ps, b, mu, rs);
    const float* ib = in + (long long)b * (DIM * LC);
#pragma unroll
    for (int it = 0; it < 8; it++) {
        int idx = threadIdx.x + it * 256;
        int dd = idx >> 6, l = idx & 63;
        int d = d0 + dd;
        float v = (ib[(long long)d * 64 + l] - mu) * rs * lw[d * 64 + l] + lb[d * 64 + l];
        sm[dd][l] = v;
    }
    __syncthreads();
    __half* ob = out + (long long)b * 64 * 768;
#pragma unroll
    for (int it = 0; it < 8; it++) {
        int idx = threadIdx.x + it * 256;
        int l = idx >> 5, dd = idx & 31;
        ob[(long long)l * 768 + d0 + dd] = __float2half(sm[dd][l]);
    }
}

// ---------------------------------------------------------------------------
// Small kernels
// ---------------------------------------------------------------------------
__global__ void wconv_k(const float* __restrict__ src, int ld, int trans,
                        long long total, int KK, __half* __restrict__ out)
{
    long long idx = (long long)blockIdx.x * 256 + threadIdx.x;
    if (idx >= total) return;
    int n = (int)(idx / KK), k = (int)(idx % KK);
    float v = trans ? src[(long long)k * ld + n] : src[(long long)n * ld + k];
    out[idx] = __float2half(v);
}

__global__ void wconv7_k(const float* __restrict__ s0, const float* __restrict__ s1,
                         const float* __restrict__ s2, const float* __restrict__ s3,
                         const float* __restrict__ s4, const float* __restrict__ s5,
                         const float* __restrict__ s6,
                         __half* __restrict__ dst)
{
    const int wi = blockIdx.y;
    const float* src = wi == 0 ? s0 : wi == 1 ? s1 : wi == 2 ? s2 : wi == 3 ? s3
                     : wi == 4 ? s4 : wi == 5 ? s5 : s6;
    const int trans = (wi >= 3);
    long long idx = (long long)blockIdx.x * 256 + threadIdx.x;
    if (idx >= (long long)DIM * DIM) return;
    int n = (int)(idx / DIM), k = (int)(idx % DIM);
    float v = trans ? src[(long long)k * DIM + n] : src[(long long)n * DIM + k];
    dst[(long long)wi * DIM * DIM + idx] = __float2half(v);
}

// Q region: Qs + Q^T + q2 partials; 64x64 tile, fully coalesced stores
__global__ void qboth_k(const float* __restrict__ x, const float* __restrict__ w2,
                        __half* __restrict__ qs, __half* __restrict__ qt,
                        float* __restrict__ qpart)
{
    __shared__ float sm[64][65];
    const int j0 = blockIdx.x * 64, d0 = blockIdx.y * 64, b = blockIdx.z;
    const int tx = threadIdx.x & 31, ty = threadIdx.x >> 5;
    const int d = d0 + tx * 2;
    const float w2a = w2[d], w2b = w2[d + 1];
    __half2* qsb = (__half2*)(qs + (long long)b * LQ * DIM);
#pragma unroll
    for (int r = 0; r < 8; r++) {
        int j = j0 + ty + r * 8;
        float2 v = reinterpret_cast<const float2*>(x)[((long long)b * SEQ + LC + j) * (DIM / 2) + (d >> 1)];
        sm[tx * 2][ty + r * 8]     = v.x;
        sm[tx * 2 + 1][ty + r * 8] = v.y;
        qsb[(long long)j * (DIM / 2) + (d >> 1)] = __floats2half2_rn(v.x, v.y);
        float s = v.x * w2a + v.y * w2b;
#pragma unroll
        for (int o = 16; o > 0; o >>= 1) s += __shfl_down_sync(0xffffffffu, s, o);
        if (tx == 0)
            qpart[(long long)blockIdx.y * (BATCH * LQ) + (long long)b * LQ + j] = s;
    }
    __syncthreads();
    __half2* qtb = (__half2*)(qt + (long long)b * DIM * LQ);
#pragma unroll
    for (int it = 0; it < 8; it++) {
        int idx = threadIdx.x + it * 256;      // 0..2047
        int dd = idx >> 5, j2 = idx & 31;
        qtb[(long long)(d0 + dd) * (LQ / 2) + (j0 >> 1) + j2] =
            __floats2half2_rn(sm[dd][j2 * 2], sm[dd][j2 * 2 + 1]);
    }
}

// C region: cw3 + C^T + c1 partials; 64x64 tile
__global__ void cboth_k(const float* __restrict__ x, const float* __restrict__ w1,
                        const float* __restrict__ w3,
                        __half* __restrict__ cw3, __half* __restrict__ ct,
                        float* __restrict__ cpart)
{
    __shared__ float sm[64][65];
    const int d0 = blockIdx.x * 64, b = blockIdx.y;
    const int tx = threadIdx.x & 31, ty = threadIdx.x >> 5;
    const int d = d0 + tx * 2;
    const float w1a = w1[d], w1b = w1[d + 1];
    const float w3a = w3[d], w3b = w3[d + 1];
    __half2* cwb = (__half2*)(cw3 + (long long)b * LC * DIM);
#pragma unroll
    for (int r = 0; r < 8; r++) {
        int l = ty + r * 8;
        float2 v = reinterpret_cast<const float2*>(x)[((long long)b * SEQ + l) * (DIM / 2) + (d >> 1)];
        sm[tx * 2][l]     = v.x;
        sm[tx * 2 + 1][l] = v.y;
        cwb[(long long)l * (DIM / 2) + (d >> 1)] = __floats2half2_rn(v.x * w3a, v.y * w3b);
        float s = v.x * w1a + v.y * w1b;
#pragma unroll
        for (int o = 16; o > 0; o >>= 1) s += __shfl_down_sync(0xffffffffu, s, o);
        if (tx == 0)
            cpart[(long long)blockIdx.x * (BATCH * LC) + (long long)b * LC + l] = s;
    }
    __syncthreads();
    __half2* ctb = (__half2*)(ct + (long long)b * SE);
#pragma unroll
    for (int it = 0; it < 8; it++) {
        int idx = threadIdx.x + it * 256;
        int dd = idx >> 5, l2 = idx & 31;
        ctb[(long long)(d0 + dd) * (LC / 2) + l2] =
            __floats2half2_rn(sm[dd][l2 * 2], sm[dd][l2 * 2 + 1]);
    }
}

// merged reduce of q2 and c1 partials
__global__ void qcred_k(const float* __restrict__ qpart, const float* __restrict__ cpart,
                        float* __restrict__ q2, float* __restrict__ c1)
{
    int i = blockIdx.x * 256 + threadIdx.x;
    if (i < BATCH * LQ) {
        float s = 0.f;
#pragma unroll
        for (int c = 0; c < NCHUNK; c++)
            s += qpart[(long long)c * (BATCH * LQ) + i];
        q2[i] = s;
    } else {
        int k = i - BATCH * LQ;
        if (k < BATCH * LC) {
            float s = 0.f;
#pragma unroll
            for (int c = 0; c < NCHUNK; c++)
                s += cpart[(long long)c * (BATCH * LC) + k];
            c1[k] = s;
        }
    }
}

// fused dual softmax of S (fp16 in): S1 = softmax rows (axis j), S2 = softmax cols (axis i)
// one CTA per batch; E = exp(v - rm[i]) kept in smem; col softmax via E*w identity.
__global__ void __launch_bounds__(256) softmax_both_k(
    const __half* __restrict__ Sf, __half* __restrict__ S1, __half* __restrict__ S2)
{
    extern __shared__ float sb[];
    float* E  = sb;                 // [64][449]
    float* rm = sb + 64 * 449;
    float* ri = rm + 64;
    float* wv = ri + 64;
    float* ci = wv + 64;            // [448]
    __shared__ float Mv;

    const int b = blockIdx.x, tid = threadIdx.x, lane = tid & 31, wid = tid >> 5;
    const __half* Sb = Sf + (long long)b * LC * LQ;

    for (int idx = tid; idx < LC * LQ; idx += 256) {
        int i = idx / LQ, j = idx - i * LQ;
        E[i * 449 + j] = __half2float(Sb[idx]);
    }
    __syncthreads();

    // row pass: warp per row, 8 rows per warp
#pragma unroll
    for (int r = 0; r < 8; r++) {
        int i = wid + r * 8;
        float m = -1e30f;
        for (int j = lane; j < LQ; j += 32) m = fmaxf(m, E[i * 449 + j]);
#pragma unroll
        for (int o = 16; o > 0; o >>= 1) m = fmaxf(m, __shfl_xor_sync(0xffffffffu, m, o));
        float s = 0.f;
        for (int j = lane; j < LQ; j += 32) {
            float e = expf(E[i * 449 + j] - m);
            E[i * 449 + j] = e;
            s += e;
        }
#pragma unroll
        for (int o = 16; o > 0; o >>= 1) s += __shfl_xor_sync(0xffffffffu, s, o);
        if (lane == 0) { rm[i] = m; ri[i] = 1.f / s; }
    }
    __syncthreads();

    if (tid == 0) {
        float M = -1e30f;
#pragma unroll
        for (int i = 0; i < 64; i++) M = fmaxf(M, rm[i]);
        Mv = M;
    }
    __syncthreads();
    if (tid < 64) wv[tid] = expf(rm[tid] - Mv);
    __syncthreads();

    // col pass: thread per column
    for (int j = tid; j < LQ; j += 256) {
        float s = 0.f;
#pragma unroll 8
        for (int i = 0; i < 64; i++) s += E[i * 449 + j] * wv[i];
        ci[j] = 1.f / s;
    }
    __syncthreads();

    __half* o1 = S1 + (long long)b * LC * LQ;
    __half* o2 = S2 + (long long)b * LC * LQ;
    for (int idx = tid; idx < LC * LQ; idx += 256) {
        int i = idx / LQ, j = idx - i * LQ;
        float e = E[i * 449 + j];
        o1[idx] = __float2half(e * ri[i]);
        o2[idx] = __float2half(e * wv[i] * ci[j]);
    }
}

// smem-tiled concat-gather + depthwise k=5 -> Y fp16 (b,l,c)
__global__ void __launch_bounds__(256) rz_dw_tile_k(
    const float* __restrict__ x, const float* __restrict__ Abuf,
    const float* __restrict__ Btbuf,
    const float* __restrict__ dww, const float* __restrict__ dwb,
    __half* __restrict__ Y)
{
    extern __shared__ float sb[];
    float* xs = sb;
    float* as = sb + 64 * 128;
    float* bs = sb + 2 * 64 * 128;

    const int d0 = blockIdx.x * 128;
    const int b  = blockIdx.y;
    const int tid = threadIdx.x;

    {
        const float4* xp = reinterpret_cast<const float4*>(x + ((long long)b * SEQ) * DIM);
        const float4* ap = reinterpret_cast<const float4*>(Abuf + (long long)b * LC * DIM);
        const float4* bp = reinterpret_cast<const float4*>(Btbuf + (long long)b * LC * DIM);
        const int d04 = d0 >> 2;
#pragma unroll
        for (int it = 0; it < 8; it++) {
            int idx = tid + it * 256;
            int l = idx >> 5, c4 = idx & 31;
            reinterpret_cast<float4*>(xs)[idx] = xp[(long long)l * (DIM / 4) + d04 + c4];
            reinterpret_cast<float4*>(as)[idx] = ap[(long long)l * (DIM / 4) + d04 + c4];
            reinterpret_cast<float4*>(bs)[idx] = bp[(long long)l * (DIM / 4) + d04 + c4];
        }
    }
    __syncthreads();

    const int dd = tid & 127;
    const int lbase = tid >> 7;
    __half* Yb = Y + (long long)b * LC * C4;

#pragma unroll
    for (int g = 0; g < 4; g++) {
        const int c = g * DIM + d0 + dd;
        const float bias = dwb[c];
        float wv5[5];
#pragma unroll
        for (int t = 0; t < 5; t++) wv5[t] = dww[c * 5 + t];

#pragma unroll
        for (int it = 0; it < 32; it++) {
            const int l = lbase + it * 2;
            float acc = bias;
#pragma unroll
            for (int t = 0; t < 5; t++) {
                int l2 = l + t - 2;
                if (l2 < 0 || l2 >= LC) continue;
                float v;
                int o = l2 * 128 + dd;
                if (g == 0)      v = xs[o];
                else if (g == 1) v = as[o];
                else if (g == 2) v = xs[o] * as[o];
                else             v = xs[o] * bs[o];
                acc = fmaf(v, wv5[t], acc);
            }
            Yb[(long long)l * C4 + c] = __float2half(acc);
        }
    }
}

__global__ void pe_init_k(float* __restrict__ pe)
{
    int idx = blockIdx.x * 256 + threadIdx.x;
    if (idx >= DIM * LC) return;
    int d = idx / LC, l = idx % LC;
    float fd = (float)d;
    bool even = (d & 1) == 0;
    float freq = even ? powf(10000.f, -fd / 768.f)
                      : -powf(10000.f, (1.f - fd) / 768.f);
    float ph = even ? 0.f : 1.57079632679489662f;
    pe[idx] = sinf((float)l * freq + ph);
}

__global__ void final_head_k(const float* __restrict__ X, const float* __restrict__ w,
                             const float* __restrict__ bias, float* __restrict__ out)
{
    int b = blockIdx.x;
    const float* p = X + (long long)b * (DIM * LC);
    float s = 0.f;
    for (int i = threadIdx.x; i < DIM * LC; i += 256) s = fmaf(p[i], w[i], s);
    __shared__ float sh[256];
    sh[threadIdx.x] = s; __syncthreads();
    for (int o = 128; o > 0; o >>= 1) {
        if (threadIdx.x < o) sh[threadIdx.x] += sh[threadIdx.x + o];
        __syncthreads();
    }
    if (threadIdx.x == 0) out[b] = 1.f / (1.f + expf(-(sh[0] + bias[0])));
}

// ---------------------------------------------------------------------------
// Host-side helpers
// ---------------------------------------------------------------------------
template<int OMODE>
static inline void run_mgemm(const __half* Af, const __half* Bf,
                             float* O, __half* Oh, long long sO, int ldo,
                             const float* bias,
                             const float* R, long long sR,
                             const float* plane, float* psum,
                             int N, int K, int relu)
{
    cudaFuncSetAttribute((const void*)mgemm_k<OMODE>,
                         cudaFuncAttributeMaxDynamicSharedMemorySize, MT_SMEM);
    dim3 grid(N / 128, BATCH / 2);
    mgemm_k<OMODE><<<grid, 256, MT_SMEM>>>(Af, Bf, O, Oh, sO, ldo, bias, R, sR, plane, psum, K, relu);
}

static inline void run_pgemm(const __half* Af, long long sA, int lda,
                             const __half* Bf, long long sB, int ldb,
                             float* O, __half* Oh, long long sO, int ldo,
                             const float* bM, long long sbM,
                             const float* bN, long long sbN,
                             float alpha, int N, int K)
{
    cudaFuncSetAttribute((const void*)pgemm_k,
                         cudaFuncAttributeMaxDynamicSharedMemorySize, PG_SMEM);
    dim3 grid(N / 64, BATCH);
    pgemm_k<<<grid, 256, PG_SMEM>>>(Af, sA, lda, Bf, sB, ldb, O, Oh, sO, ldo,
                                    bM, sbM, bN, sbN, alpha, K);
}

static inline void run_pgemm_sm(const __half* Af, long long sA, int lda,
                                const __half* Bf, long long sB, int ldb,
                                __half* Oh, long long sO, float alpha, int K)
{
    cudaFuncSetAttribute((const void*)pgemm_sm_k,
                         cudaFuncAttributeMaxDynamicSharedMemorySize, PG_SMEM);
    dim3 grid(1, BATCH);
    pgemm_sm_k<<<grid, 256, PG_SMEM>>>(Af, sA, lda, Bf, sB, ldb, Oh, sO, alpha, K);
}

struct EncW {
    const float *c1dw, *c1db, *c1pw, *c1pb;
    const float *c2dw, *c2db, *c2pw, *c2pb;
    const float *wq, *wk, *wv, *wo;
    const float *fcw, *fcb;
    const float *nbw, *nbb, *n1w, *n1b, *n2w, *n2b, *nEw, *nEb;
};

struct HfW {
    __half *rz, *c1, *c2, *fc, *qkv, *wo;
};

// Xin's LN stats must already be in psum (written by the producing mgemm).
static void enc_block(const float* Xin,
                      float* t2, float* t3,
                      __half* qkf, __half* vT, __half* attnf,
                      float* Xout, const float* outPlane, float* outPsum,
                      float* psum,
                      const EncW& w, const HfW& hw,
                      __half* a1, __half* a2)
{
    const float scale = 0.03608439182435161f; // 1/sqrt(768)
    const long long SQK = 64LL * 1536;
    const long long SAT = 64LL * 64;

    ln_conv_t_k<<<dim3(BATCH, 24), 256>>>(Xin, psum, w.nbw, w.nbb, w.c1dw, w.c1db, a1);
    run_mgemm<1>(a1, hw.c1, t2, nullptr, SE, 64, w.c1pb, Xin, SE, nullptr, psum, DIM, DIM, 1);
    ln_conv_t_k<<<dim3(BATCH, 24), 256>>>(t2, psum, w.n1w, w.n1b, w.c2dw, w.c2db, a1);
    run_mgemm<1>(a1, hw.c2, t3, nullptr, SE, 64, w.c2pb, t2, SE, nullptr, psum, DIM, DIM, 1);
    ln_apply_t_k<<<dim3(BATCH, 24), 256>>>(t3, psum, w.n2w, w.n2b, a1);
    run_mgemm<0>(a1, hw.qkv, nullptr, qkf, SQK, 1536, nullptr, nullptr, 0, nullptr, nullptr, 1536, DIM, 0);
    run_mgemm<1>(a1, hw.qkv + 2LL * DIM * DIM, nullptr, vT, SE, 64,
                 nullptr, nullptr, 0, nullptr, nullptr, DIM, DIM, 0);
    run_pgemm_sm(qkf, SQK, 1536, qkf + DIM, SQK, 1536, attnf, SAT, scale, DIM);
    run_pgemm(attnf, SAT, 64, vT, SE, 64,
              nullptr, a2, SE, DIM, nullptr, 0, nullptr, 0, 1.f, DIM, LC);
    run_mgemm<1>(a2, hw.wo, t2, nullptr, SE, 64, nullptr, t3, SE, nullptr, psum, DIM, DIM, 0);
    ln_apply_t_k<<<dim3(BATCH, 24), 256>>>(t2, psum, w.nEw, w.nEb, a1);
    run_mgemm<1>(a1, hw.fc, Xout, nullptr, SE, 64, w.fcb, t2, SE, outPlane, outPsum, DIM, DIM, 1);
}

// ---------------------------------------------------------------------------
// Entry point
// ---------------------------------------------------------------------------
extern "C" void kernel_launch(void* const* d_in, const int* in_sizes, int n_in,
                              void* d_out, int out_size)
{
    (void)in_sizes; (void)n_in; (void)out_size;
    const float* x       = (const float*)d_in[0];
    const float* Wv      = (const float*)d_in[1];
    const float* rz_dw_w = (const float*)d_in[2];
    const float* rz_dw_b = (const float*)d_in[3];
    const float* rz_pw_w = (const float*)d_in[4];
    const float* rz_pw_b = (const float*)d_in[5];
    EncW w;
    w.c1dw = (const float*)d_in[6];  w.c1db = (const float*)d_in[7];
    w.c1pw = (const float*)d_in[8];  w.c1pb = (const float*)d_in[9];
    w.c2dw = (const float*)d_in[10]; w.c2db = (const float*)d_in[11];
    w.c2pw = (const float*)d_in[12]; w.c2pb = (const float*)d_in[13];
    w.wq   = (const float*)d_in[14]; w.wk   = (const float*)d_in[15];
    w.wv   = (const float*)d_in[16]; w.wo   = (const float*)d_in[17];
    w.fcw  = (const float*)d_in[18]; w.fcb  = (const float*)d_in[19];
    w.nbw  = (const float*)d_in[20]; w.nbb  = (const float*)d_in[21];
    w.n1w  = (const float*)d_in[22]; w.n1b  = (const float*)d_in[23];
    w.n2w  = (const float*)d_in[24]; w.n2b  = (const float*)d_in[25];
    w.nEw  = (const float*)d_in[26]; w.nEb  = (const float*)d_in[27];
    const float* fcf_w = (const float*)d_in[28];
    const float* fcf_b = (const float*)d_in[29];

    float* pool = nullptr;
    cudaGetSymbolAddress((void**)&pool, g_pool);

    float* c1s  = pool + OFF_C1;
    float* q2s  = pool + OFF_Q2;
    float* Abuf = pool + OFF_A;
    float* Btb  = pool + OFF_BT;
    float* E[8];
    for (int i = 0; i < 8; i++) E[i] = pool + OFF_E0 + (long long)i * SZ_E;
    float* pe   = pool + OFF_PE;
    float* psum = pool + OFF_PS;
    float* qpart = pool + OFF_Y;
    float* cpart = pool + OFF_Y + (long long)NCHUNK * BATCH * LQ;

    __half* cw3f  = (__half*)(pool + OFF_CW3);
    __half* Sf    = (__half*)(pool + OFF_S);
    __half* S1f   = (__half*)(pool + OFF_S1);
    __half* S2f   = (__half*)(pool + OFF_S2);
    __half* Yf    = (__half*)(pool + OFF_Y);
    __half* Qsf   = (__half*)(pool + OFF_QS);
    __half* Qtf   = (__half*)(pool + OFF_QT);
    __half* a1    = (__half*)(pool + OFF_ACT);
    __half* a2    = a1 + SZ_BD;
    __half* qkf   = (__half*)E[4];
    __half* vT    = (__half*)E[5];
    __half* attnf = (__half*)E[6];
    __half* Tf    = (__half*)E[6];
    __half* cTf   = (__half*)E[1];

    HfW hw;
    {
        __half* p = (__half*)(pool + OFF_WB);
        hw.rz  = p; p += (long long)DIM * C4;
        hw.c1  = p; p += (long long)DIM * DIM;
        hw.c2  = p; p += (long long)DIM * DIM;
        hw.fc  = p; p += (long long)DIM * DIM;
        hw.qkv = p; p += 3LL * DIM * DIM;
        hw.wo  = p;
    }

    const long long WDD = (long long)DIM * DIM;

    pe_init_k<<<(DIM * LC + 255) / 256, 256>>>(pe);
    cboth_k<<<dim3(NCHUNK, BATCH), 256>>>(x, Wv, Wv + 2 * DIM, cw3f, cTf, cpart);
    qboth_k<<<dim3(LQ / 64, NCHUNK, BATCH), 256>>>(x, Wv + DIM, Qsf, Qtf, qpart);
    qcred_k<<<(BATCH * (LQ + LC)) / 256, 256>>>(qpart, cpart, q2s, c1s);

    // S = cw3 @ Q^T + c1[:,None] + q2[None,:]   (tensor, per-batch) -> fp16
    run_pgemm(cw3f, 64LL * DIM, DIM, Qsf, (long long)LQ * DIM, DIM,
              nullptr, Sf, (long long)LC * LQ, LQ, c1s, LC, q2s, LQ, 1.f, LQ, DIM);

    // fused dual softmax -> S1, S2 fp16
    cudaFuncSetAttribute((const void*)softmax_both_k,
                         cudaFuncAttributeMaxDynamicSharedMemorySize, SB_SMEM);
    softmax_both_k<<<BATCH, 256, SB_SMEM>>>(Sf, S1f, S2f);

    // A = S1 @ Q (tensor; B = Q^T) -> fp32
    run_pgemm(S1f, (long long)LC * LQ, LQ, Qtf, (long long)DIM * LQ, LQ,
              Abuf, nullptr, (long long)LC * DIM, DIM, nullptr, 0, nullptr, 0, 1.f, DIM, LQ);

    // T = S1 @ S2^T (tensor) -> fp16
    run_pgemm(S1f, (long long)LC * LQ, LQ, S2f, (long long)LC * LQ, LQ,
              nullptr, Tf, (long long)LC * LC, LC, nullptr, 0, nullptr, 0, 1.f, LC, LQ);

    // Bt = T @ C (tensor; B = C^T) -> fp32
    run_pgemm(Tf, (long long)LC * LC, LC, cTf, SE, LC,
              Btb, nullptr, (long long)LC * DIM, DIM, nullptr, 0, nullptr, 0, 1.f, DIM, LC);

    // smem-tiled concat-gather + depthwise k=5 -> Y fp16 (b,l,c)
    cudaFuncSetAttribute((const void*)rz_dw_tile_k,
                         cudaFuncAttributeMaxDynamicSharedMemorySize, RZ_SMEM);
    rz_dw_tile_k<<<dim3(DIM / 128, BATCH), 256, RZ_SMEM>>>(x, Abuf, Btb, rz_dw_w, rz_dw_b, Yf);

    // ---- weight conversion (fp16, n x k, k-contiguous) ----
    {
        long long trz = (long long)DIM * C4;
        wconv_k<<<(int)((trz + 255) / 256), 256>>>(rz_pw_w, C4, 0, trz, C4, hw.rz);
        int gs = (int)((WDD + 255) / 256);
        wconv7_k<<<dim3(gs, 7), 256>>>(w.c1pw, w.c2pw, w.fcw, w.wq, w.wk, w.wv, w.wo, hw.c1);
    }

    // pointwise 3072 -> 768 (mma): +bias +pe -> E0 (b,d,l), + LN stats
    run_mgemm<1>(Yf, hw.rz, E[0], nullptr, SE, 64, rz_pw_b, nullptr, 0, pe, psum, DIM, C4, 0);

    // ---- two encoder blocks ----
    enc_block(E[0], E[2], E[3], qkf, vT, attnf, E[7], pe, psum, psum, w, hw, a1, a2);
    enc_block(E[7], E[2], E[3], qkf, vT, attnf, E[0], nullptr, nullptr, psum, w, hw, a1, a2);

    // ---- final sigmoid head ----
    final_head_k<<<BATCH, 256>>>(E[0], fcf_w, fcf_b, (float*)d_out);
}